// round 9
// baseline (speedup 1.0000x reference)
#include <cuda_runtime.h>
#include <cstdint>

#define N_ATOMS 50000
#define N_PAIRS 1600000
#define LN2F 0.6931471805599453f

__device__ float g_x[(size_t)N_ATOMS * 128];
__device__ float g_acc[(size_t)N_ATOMS * 128];
__device__ int   g_cnt[N_ATOMS];
__device__ int   g_pos[N_ATOMS];
__device__ int2  g_ord[(size_t)N_PAIRS];   // (p, idx_j) in idx_i-sorted order
__device__ int   g_si[(size_t)N_PAIRS];    // idx_i in sorted order

// ---------------------------------------------------------------------------
// helpers
// ---------------------------------------------------------------------------
__device__ __forceinline__ uint32_t f2tf32(float x) {
    uint32_t u; asm("cvt.rna.tf32.f32 %0, %1;" : "=r"(u) : "f"(x)); return u;
}
__device__ __forceinline__ float tf32f(float x) { return __uint_as_float(f2tf32(x)); }

__device__ __forceinline__ float fssp(float x) {
    if (x > 60.f) return x - LN2F;
    float t, l;
    asm("ex2.approx.f32 %0, %1;" : "=f"(t) : "f"(x * 1.4426950408889634f));
    asm("lg2.approx.f32 %0, %1;" : "=f"(l) : "f"(t + 1.0f));
    return 0.69314718055994531f * (l - 1.0f);
}
__device__ __forceinline__ void red_add_v4(float* p, float a, float b, float c, float d) {
    asm volatile("red.global.add.v4.f32 [%0], {%1, %2, %3, %4};"
                 :: "l"(p), "f"(a), "f"(b), "f"(c), "f"(d) : "memory");
}
__device__ __forceinline__ void barh(int id) {
    asm volatile("bar.sync %0, 256;" :: "r"(id) : "memory");
}
__device__ __forceinline__ void mma8(float c[4], const uint32_t a[4], const uint32_t b[2]) {
    asm volatile(
        "mma.sync.aligned.m16n8k8.row.col.f32.tf32.tf32.f32 "
        "{%0,%1,%2,%3}, {%4,%5,%6,%7}, {%8,%9}, {%0,%1,%2,%3};\n"
        : "+f"(c[0]), "+f"(c[1]), "+f"(c[2]), "+f"(c[3])
        : "r"(a[0]), "r"(a[1]), "r"(a[2]), "r"(a[3]), "r"(b[0]), "r"(b[1]));
}

// ---------------------------------------------------------------------------
// Fragment-major smem layouts (round-5 derivation)
// ---------------------------------------------------------------------------
__device__ __forceinline__ int afrag_idx(int r, int c, int kst) {
    int lane = (r & 7) * 4 + (c & 3);
    int slot = ((r >> 3) & 1) + ((c >> 2) & 1) * 2;
    return (r >> 5) * (kst * 256) + (c >> 3) * 256 + ((r >> 4) & 1) * 128 + lane * 4 + slot;
}
__device__ __forceinline__ int bfrag_idx(int kk, int n, int kst) {
    int j = (n >> 3) & 7;
    int lane = (n & 7) * 4 + (kk & 3);
    int slot = (j & 1) * 2 + ((kk >> 2) & 1);
    return (n >> 6) * (kst * 512) + (kk >> 3) * 512 + (j >> 1) * 128 + lane * 4 + slot;
}

template <int KST>
__device__ __forceinline__ void gemmF(const float* __restrict__ Af,
                                      const float* __restrict__ Bf,
                                      float C[2][8][4], int htid) {
    const int lane = htid & 31, warp = htid >> 5;
    const float4* A4 = (const float4*)Af + (warp >> 1) * (KST * 64) + lane;
    const float4* B4 = (const float4*)Bf + (warp & 1) * (KST * 128) + lane;
#pragma unroll
    for (int k = 0; k < KST; ++k) {
        float4 fa0 = A4[k * 64];
        float4 fa1 = A4[k * 64 + 32];
        uint32_t a[2][4] = {
            {__float_as_uint(fa0.x), __float_as_uint(fa0.y), __float_as_uint(fa0.z), __float_as_uint(fa0.w)},
            {__float_as_uint(fa1.x), __float_as_uint(fa1.y), __float_as_uint(fa1.z), __float_as_uint(fa1.w)}};
        uint32_t b[8][2];
#pragma unroll
        for (int g = 0; g < 4; ++g) {
            float4 fb = B4[k * 128 + g * 32];
            b[2 * g][0] = __float_as_uint(fb.x);
            b[2 * g][1] = __float_as_uint(fb.y);
            b[2 * g + 1][0] = __float_as_uint(fb.z);
            b[2 * g + 1][1] = __float_as_uint(fb.w);
        }
#pragma unroll
        for (int i = 0; i < 2; ++i)
#pragma unroll
            for (int j = 0; j < 8; ++j) mma8(C[i][j], a[i], b[j]);
    }
}

// smem float offsets for k_pair
#define OFF_BF2  0
#define OFF_BF1  16384
#define OFF_BB1  19456
#define OFF_BB2  19584
#define OFF_UNI0 19712
#define UNI_W    16896                        // union: A1/A2 fragments or w rows [128][132]
#define HALF_STRIDE (UNI_W + 128 + 128 + 128) // + scut + ssj + ssi
#define SMEM_PAIR_F (OFF_UNI0 + 2 * HALF_STRIDE)  // 54272 f = 217088 B

// classic strided-smem GEMM for k_proj / k_out
template <int KSTEPS, int ASTRIDE, int BSTRIDE>
__device__ __forceinline__ void gemm128(const float* __restrict__ As,
                                        const float* __restrict__ Bs,
                                        float C[2][8][4], int tid) {
    const int lane = tid & 31, warp = tid >> 5;
    const int wm = (warp >> 1) * 32, wn = (warp & 1) * 64;
    const int gid = lane >> 2, tig = lane & 3;
#pragma unroll
    for (int k = 0; k < KSTEPS; ++k) {
        uint32_t a[2][4];
#pragma unroll
        for (int i = 0; i < 2; ++i) {
            const float* ap = As + (wm + i * 16 + gid) * ASTRIDE + k * 8 + tig;
            a[i][0] = __float_as_uint(ap[0]);
            a[i][1] = __float_as_uint(ap[8 * ASTRIDE]);
            a[i][2] = __float_as_uint(ap[4]);
            a[i][3] = __float_as_uint(ap[8 * ASTRIDE + 4]);
        }
        uint32_t b[8][2];
#pragma unroll
        for (int j = 0; j < 8; ++j) {
            const float* bp = Bs + (k * 8 + tig) * BSTRIDE + wn + j * 8 + gid;
            b[j][0] = __float_as_uint(bp[0]);
            b[j][1] = __float_as_uint(bp[4 * BSTRIDE]);
        }
#pragma unroll
        for (int i = 0; i < 2; ++i)
#pragma unroll
            for (int j = 0; j < 8; ++j) mma8(C[i][j], a[i], b[j]);
    }
}

// ---------------------------------------------------------------------------
// sort-by-idx_i machinery
// ---------------------------------------------------------------------------
__global__ void k_czero() {
    int i = blockIdx.x * blockDim.x + threadIdx.x;
    if (i < N_ATOMS) g_cnt[i] = 0;
}
__global__ void k_zeroacc() {
    size_t i = (size_t)blockIdx.x * blockDim.x + threadIdx.x;
    if (i < (size_t)N_ATOMS * 32)
        reinterpret_cast<float4*>(g_acc)[i] = make_float4(0.f, 0.f, 0.f, 0.f);
}
__global__ void k_count(const int* __restrict__ pidx) {
    int p = blockIdx.x * blockDim.x + threadIdx.x;
    if (p < N_PAIRS) atomicAdd(&g_cnt[__ldg(&pidx[p])], 1);
}
__global__ __launch_bounds__(1024, 1) void k_scan() {
    __shared__ int part[1024];
    const int tid = threadIdx.x;
    const int PER = 49;  // 1024*49 = 50176 >= 50000
    int b = tid * PER;
    int s = 0;
    for (int q = 0; q < PER; ++q) {
        int i = b + q;
        if (i < N_ATOMS) s += g_cnt[i];
    }
    part[tid] = s;
    __syncthreads();
    for (int off = 1; off < 1024; off <<= 1) {
        int v = (tid >= off) ? part[tid - off] : 0;
        __syncthreads();
        part[tid] += v;
        __syncthreads();
    }
    int run = tid ? part[tid - 1] : 0;
    for (int q = 0; q < PER; ++q) {
        int i = b + q;
        if (i < N_ATOMS) {
            int c = g_cnt[i];
            g_pos[i] = run;
            run += c;
        }
    }
}
__global__ void k_place(const int* __restrict__ pidx) {
    int p = blockIdx.x * blockDim.x + threadIdx.x;
    if (p < N_PAIRS) {
        int i = __ldg(&pidx[p]);
        int j = __ldg(&pidx[N_PAIRS + p]);
        int pos = atomicAdd(&g_pos[i], 1);
        g_ord[pos] = make_int2(p, j);
        g_si[pos] = i;
    }
}

// ---------------------------------------------------------------------------
// x = atomic_embedding @ W_in -> g_x
// ---------------------------------------------------------------------------
__global__ __launch_bounds__(256, 2) void k_proj(const float* __restrict__ emb,
                                                 const float* __restrict__ W_in) {
    extern __shared__ float smem[];
    float* As = smem;
    float* Bs = smem + 128 * 132;
    const int tid = threadIdx.x;
    const int r0 = blockIdx.x * 128;
    for (int t = tid; t < 128 * 132; t += 256) {
        int r = t / 132, c = t % 132;
        float v = 0.f;
        if (c < 128 && (r0 + r) < N_ATOMS) v = emb[(size_t)(r0 + r) * 128 + c];
        As[t] = tf32f(v);
    }
    for (int t = tid; t < 128 * 136; t += 256) {
        int r = t / 136, c = t % 136;
        Bs[t] = (c < 128) ? tf32f(W_in[r * 128 + c]) : 0.f;
    }
    __syncthreads();
    float C[2][8][4] = {};
    gemm128<16, 132, 136>(As, Bs, C, tid);
    const int lane = tid & 31, warp = tid >> 5;
    const int wm = (warp >> 1) * 32, wn = (warp & 1) * 64;
    const int gid = lane >> 2, tig = lane & 3;
#pragma unroll
    for (int i = 0; i < 2; ++i)
#pragma unroll
        for (int h = 0; h < 2; ++h) {
            int row = r0 + wm + i * 16 + gid + h * 8;
            if (row < N_ATOMS)
#pragma unroll
                for (int j = 0; j < 8; ++j) {
                    int col = wn + j * 8 + 2 * tig;
                    float2 v = make_float2(C[i][j][h * 2], C[i][j][h * 2 + 1]);
                    *reinterpret_cast<float2*>(&g_x[(size_t)row * 128 + col]) = v;
                }
        }
}

// ---------------------------------------------------------------------------
// Fused pair kernel on idx_i-sorted pairs: filter GEMMs + in-tile segment sum.
// 512 threads = two independent 256-thread halves; weights shared.
// ---------------------------------------------------------------------------
__global__ __launch_bounds__(512, 1)
void k_pair(const float* __restrict__ f_ij, const float* __restrict__ cut,
            const float* __restrict__ W_f1, const float* __restrict__ b_f1,
            const float* __restrict__ W_f2, const float* __restrict__ b_f2,
            int tile_base, int tile_count) {
    extern __shared__ float smem[];
    const int tid = threadIdx.x;
    const int half = tid >> 8;
    const int htid = tid & 255;

    float* Bf2 = smem + OFF_BF2;
    float* Bf1 = smem + OFF_BF1;
    float* uni = smem + OFF_UNI0 + half * HALF_STRIDE;
    float* scut = uni + UNI_W;
    int*   ssj  = (int*)(scut + 128);
    int*   ssi  = ssj + 128;

    for (int t = tid; t < 128 * 128; t += 512) {
        int kk = t >> 7, n = t & 127;
        Bf2[bfrag_idx(kk, n, 16)] = tf32f(W_f2[kk * 128 + n]);
    }
    for (int t = tid; t < 24 * 128; t += 512) {
        int kk = t >> 7, n = t & 127;
        Bf1[bfrag_idx(kk, n, 3)] = (kk < 20) ? tf32f(W_f1[kk * 128 + n]) : 0.f;
    }
    if (tid < 128) smem[OFF_BB1 + tid] = b_f1[tid];
    else if (tid < 256) smem[OFF_BB2 + tid - 128] = b_f2[tid - 128];
    for (int t = htid; t < 3072; t += 256) uni[t] = 0.f;  // first-tile A1 pad
    __syncthreads();

    const float* b1s = smem + OFF_BB1;
    const float* b2s = smem + OFF_BB2;
    const int bar = 1 + half;
    const int lane = htid & 31, warp = htid >> 5;
    const int wm = (warp >> 1) * 32, wn = (warp & 1) * 64;
    const int gid = lane >> 2, tig = lane & 3;

    const int end = tile_base + tile_count;
    const int step = (int)gridDim.x * 2;
    int tile = tile_base + (int)blockIdx.x * 2 + half;
    if (tile >= end) return;

    const int prow = htid >> 1;
    const int pcol = (htid & 1) * 10;
    float pf[10];
    float pcut = 0.f;
    int pjj = 0, pii = 0;
    {
        const int pos0 = tile * 128;
        int2 ord = __ldg(&g_ord[pos0 + prow]);
        const float* src = f_ij + (size_t)ord.x * 20 + pcol;
#pragma unroll
        for (int q = 0; q < 10; ++q) pf[q] = tf32f(__ldg(src + q));
        if (htid < 128) {
            int2 o2 = __ldg(&g_ord[pos0 + htid]);
            pjj = o2.y;
            pii = __ldg(&g_si[pos0 + htid]);
            pcut = __ldg(&cut[o2.x]);
        }
    }

    for (; tile < end; tile += step) {
        // S1: prefetched f_ij -> fragment-major A1 + meta
#pragma unroll
        for (int q = 0; q < 10; ++q) uni[afrag_idx(prow, pcol + q, 3)] = pf[q];
        if (htid < 128) { scut[htid] = pcut; ssj[htid] = pjj; ssi[htid] = pii; }
        barh(bar);

        // prefetch next tile
        int nt = tile + step;
        if (nt < end) {
            const int pos0 = nt * 128;
            int2 ord = __ldg(&g_ord[pos0 + prow]);
            const float* src = f_ij + (size_t)ord.x * 20 + pcol;
#pragma unroll
            for (int q = 0; q < 10; ++q) pf[q] = tf32f(__ldg(src + q));
            if (htid < 128) {
                int2 o2 = __ldg(&g_ord[pos0 + htid]);
                pjj = o2.y;
                pii = __ldg(&g_si[pos0 + htid]);
                pcut = __ldg(&cut[o2.x]);
            }
        }

        // GEMM1 (K=24)
        float C[2][8][4] = {};
        gemmF<3>(uni, Bf1, C, htid);
        barh(bar);

        // S3: hidden = tf32(fssp(C+b1)) -> fragment-major A2
#pragma unroll
        for (int i = 0; i < 2; ++i) {
            int r = wm + i * 16 + gid;
#pragma unroll
            for (int j = 0; j < 8; ++j) {
                int col = wn + j * 8 + 2 * tig;
                uni[afrag_idx(r, col, 16)]         = tf32f(fssp(C[i][j][0] + b1s[col]));
                uni[afrag_idx(r, col + 1, 16)]     = tf32f(fssp(C[i][j][1] + b1s[col + 1]));
                uni[afrag_idx(r + 8, col, 16)]     = tf32f(fssp(C[i][j][2] + b1s[col]));
                uni[afrag_idx(r + 8, col + 1, 16)] = tf32f(fssp(C[i][j][3] + b1s[col + 1]));
            }
        }
        barh(bar);

        // GEMM2 (K=128)
        float C2[2][8][4] = {};
        gemmF<16>(uni, Bf2, C2, htid);
        barh(bar);

        // stage w = (C2+b2)*cut rows (stride 132)
#pragma unroll
        for (int i = 0; i < 2; ++i)
#pragma unroll
            for (int h = 0; h < 2; ++h) {
                int r = wm + i * 16 + gid + h * 8;
                float ct = scut[r];
#pragma unroll
                for (int j = 0; j < 8; ++j) {
                    int col = wn + j * 8 + 2 * tig;
                    float2 v = make_float2((C2[i][j][h * 2] + b2s[col]) * ct,
                                           (C2[i][j][h * 2 + 1] + b2s[col + 1]) * ct);
                    *reinterpret_cast<float2*>(&uni[r * 132 + col]) = v;
                }
            }
        barh(bar);

        // in-tile segment sum: warp walks 16 consecutive sorted rows
        {
            const int base = warp * 16;
            int cur = ssi[base];
            float4 acc = make_float4(0.f, 0.f, 0.f, 0.f);
#pragma unroll
            for (int g = 0; g < 4; ++g) {
                float4 wv[4], xv[4];
#pragma unroll
                for (int r = 0; r < 4; ++r) {
                    int row = base + g * 4 + r;
                    wv[r] = *reinterpret_cast<const float4*>(uni + row * 132 + lane * 4);
                    xv[r] = __ldg((const float4*)(g_x + (size_t)ssj[row] * 128) + lane);
                }
#pragma unroll
                for (int r = 0; r < 4; ++r) {
                    int iv = ssi[base + g * 4 + r];
                    if (iv != cur) {
                        red_add_v4(g_acc + (size_t)cur * 128 + lane * 4,
                                   acc.x, acc.y, acc.z, acc.w);
                        acc = make_float4(0.f, 0.f, 0.f, 0.f);
                        cur = iv;
                    }
                    acc.x += wv[r].x * xv[r].x;
                    acc.y += wv[r].y * xv[r].y;
                    acc.z += wv[r].z * xv[r].z;
                    acc.w += wv[r].w * xv[r].w;
                }
            }
            red_add_v4(g_acc + (size_t)cur * 128 + lane * 4, acc.x, acc.y, acc.z, acc.w);
        }
        barh(bar);  // uni/ssi/ssj reads done before next S1 overwrite
    }
}

// ---------------------------------------------------------------------------
// Output MLP
// ---------------------------------------------------------------------------
__global__ __launch_bounds__(256, 2) void k_out(const float* __restrict__ W_o1,
                                                const float* __restrict__ b_o1,
                                                const float* __restrict__ W_o2,
                                                const float* __restrict__ b_o2,
                                                float* __restrict__ out) {
    extern __shared__ float smem[];
    float* As = smem;
    float* Bs = smem + 128 * 132;
    float* sbv = Bs + 128 * 136;
    const int tid = threadIdx.x;
    const int r0 = blockIdx.x * 128;
    for (int t = tid; t < 128 * 132; t += 256) {
        int r = t / 132, c = t % 132;
        float v = 0.f;
        if (c < 128 && (r0 + r) < N_ATOMS) v = g_acc[(size_t)(r0 + r) * 128 + c];
        As[t] = tf32f(v);
    }
    for (int t = tid; t < 128 * 136; t += 256) {
        int r = t / 136, c = t % 136;
        Bs[t] = (c < 128) ? tf32f(W_o1[r * 128 + c]) : 0.f;
    }
    if (tid < 128) sbv[tid] = b_o1[tid];
    __syncthreads();
    float C[2][8][4] = {};
    gemm128<16, 132, 136>(As, Bs, C, tid);
    __syncthreads();
    const int lane = tid & 31, warp = tid >> 5;
    const int wm = (warp >> 1) * 32, wn = (warp & 1) * 64;
    const int gid = lane >> 2, tig = lane & 3;
#pragma unroll
    for (int i = 0; i < 2; ++i) {
        int r = wm + i * 16 + gid;
#pragma unroll
        for (int j = 0; j < 8; ++j) {
            int col = wn + j * 8 + 2 * tig;
            As[r * 132 + col]           = tf32f(fssp(C[i][j][0] + sbv[col]));
            As[r * 132 + col + 1]       = tf32f(fssp(C[i][j][1] + sbv[col + 1]));
            As[(r + 8) * 132 + col]     = tf32f(fssp(C[i][j][2] + sbv[col]));
            As[(r + 8) * 132 + col + 1] = tf32f(fssp(C[i][j][3] + sbv[col + 1]));
        }
    }
    for (int t = tid; t < 128 * 136; t += 256) {
        int r = t / 136, c = t % 136;
        Bs[t] = (c < 128) ? tf32f(W_o2[r * 128 + c]) : 0.f;
    }
    if (tid < 128) sbv[tid] = b_o2[tid];
    __syncthreads();
    float C2[2][8][4] = {};
    gemm128<16, 132, 136>(As, Bs, C2, tid);
#pragma unroll
    for (int i = 0; i < 2; ++i)
#pragma unroll
        for (int h = 0; h < 2; ++h) {
            int row = r0 + wm + i * 16 + gid + h * 8;
            if (row < N_ATOMS)
#pragma unroll
                for (int j = 0; j < 8; ++j) {
                    int col = wn + j * 8 + 2 * tig;
                    float2 v = make_float2(C2[i][j][h * 2] + sbv[col],
                                           C2[i][j][h * 2 + 1] + sbv[col + 1]);
                    *reinterpret_cast<float2*>(&out[(size_t)row * 128 + col]) = v;
                }
        }
}

extern "C" void kernel_launch(void* const* d_in, const int* in_sizes, int n_in,
                              void* d_out, int out_size) {
    const float* emb  = (const float*)d_in[0];
    const int*   pidx = (const int*)d_in[1];
    const float* fij  = (const float*)d_in[2];
    const float* cut  = (const float*)d_in[3];
    const float* W_in = (const float*)d_in[4];
    const float* W_f1 = (const float*)d_in[5];
    const float* b_f1 = (const float*)d_in[6];
    const float* W_f2 = (const float*)d_in[7];
    const float* b_f2 = (const float*)d_in[8];
    const float* W_o1 = (const float*)d_in[9];
    const float* b_o1 = (const float*)d_in[10];
    const float* W_o2 = (const float*)d_in[11];
    const float* b_o2 = (const float*)d_in[12];
    float* out = (float*)d_out;

    const int smemPair = SMEM_PAIR_F * 4;  // 217088 B
    const int smemGemm = (128 * 132 + 128 * 136 + 128) * 4;

    cudaFuncSetAttribute(k_pair, cudaFuncAttributeMaxDynamicSharedMemorySize, smemPair);
    cudaFuncSetAttribute(k_proj, cudaFuncAttributeMaxDynamicSharedMemorySize, smemGemm);
    cudaFuncSetAttribute(k_out,  cudaFuncAttributeMaxDynamicSharedMemorySize, smemGemm);

    const int NT = N_PAIRS / 128;  // 12500
    k_czero<<<(N_ATOMS + 255) / 256, 256>>>();
    k_zeroacc<<<(N_ATOMS * 32 + 255) / 256, 256>>>();
    k_count<<<(N_PAIRS + 255) / 256, 256>>>(pidx);
    k_scan<<<1, 1024>>>();
    k_place<<<(N_PAIRS + 255) / 256, 256>>>(pidx);
    k_proj<<<(N_ATOMS + 127) / 128, 256, smemGemm>>>(emb, W_in);
    k_pair<<<148, 512, smemPair>>>(fij, cut, W_f1, b_f1, W_f2, b_f2, 0, NT / 2);
    k_pair<<<148, 512, smemPair>>>(fij, cut, W_f1, b_f1, W_f2, b_f2, NT / 2, NT - NT / 2);
    k_out<<<(N_ATOMS + 127) / 128, 256, smemGemm>>>(W_o1, b_o1, W_o2, b_o2, out);
}

// round 12
// speedup vs baseline: 1.8316x; 1.8316x over previous
#include <cuda_runtime.h>
#include <cuda_fp16.h>
#include <cstdint>

#define N_ATOMS 50000
#define N_PAIRS 1600000
#define LN2F 0.6931471805599453f
#define CAP 96

__device__ float g_x[(size_t)N_ATOMS * 128];
__device__ float g_acc[(size_t)N_ATOMS * 128];
__device__ float g_w[(size_t)N_PAIRS * 128];     // cutoff-weighted filters (fp32!)
__device__ int   g_cnt[N_ATOMS];
__device__ int2  g_bucket[(size_t)N_ATOMS * CAP];

// ---------------------------------------------------------------------------
// helpers
// ---------------------------------------------------------------------------
__device__ __forceinline__ uint32_t f2tf32(float x) {
    uint32_t u; asm("cvt.rna.tf32.f32 %0, %1;" : "=r"(u) : "f"(x)); return u;
}
__device__ __forceinline__ float tf32f(float x) { return __uint_as_float(f2tf32(x)); }

__device__ __forceinline__ float fssp(float x) {
    if (x > 60.f) return x - LN2F;
    float t, l;
    asm("ex2.approx.f32 %0, %1;" : "=f"(t) : "f"(x * 1.4426950408889634f));
    asm("lg2.approx.f32 %0, %1;" : "=f"(l) : "f"(t + 1.0f));
    return 0.69314718055994531f * (l - 1.0f);
}
__device__ __forceinline__ void barh(int id) {
    asm volatile("bar.sync %0, 256;" :: "r"(id) : "memory");
}
__device__ __forceinline__ uint32_t packh2(float a, float b) {
    __half2 h = __floats2half2_rn(a, b);
    return *reinterpret_cast<uint32_t*>(&h);
}
// tf32 mma (k_proj / k_out)
__device__ __forceinline__ void mma8(float c[4], const uint32_t a[4], const uint32_t b[2]) {
    asm volatile(
        "mma.sync.aligned.m16n8k8.row.col.f32.tf32.tf32.f32 "
        "{%0,%1,%2,%3}, {%4,%5,%6,%7}, {%8,%9}, {%0,%1,%2,%3};\n"
        : "+f"(c[0]), "+f"(c[1]), "+f"(c[2]), "+f"(c[3])
        : "r"(a[0]), "r"(a[1]), "r"(a[2]), "r"(a[3]), "r"(b[0]), "r"(b[1]));
}
// fp16 mma (k_pair)
__device__ __forceinline__ void mma16(float c[4], const uint32_t a[4], const uint32_t b[2]) {
    asm volatile(
        "mma.sync.aligned.m16n8k16.row.col.f32.f16.f16.f32 "
        "{%0,%1,%2,%3}, {%4,%5,%6,%7}, {%8,%9}, {%0,%1,%2,%3};\n"
        : "+f"(c[0]), "+f"(c[1]), "+f"(c[2]), "+f"(c[3])
        : "r"(a[0]), "r"(a[1]), "r"(a[2]), "r"(a[3]), "r"(b[0]), "r"(b[1]));
}

// ---------------------------------------------------------------------------
// fp16 fragment-major word indexing (m16n8k16)
// A word for element pair (row, c, c+1), c even:
//   wr=row>>5, i=(row>>4)&1, gid=row&7, hi=(row>>3)&1
//   k=c>>4, kin=c&15, khalf=kin>>3, tig=(kin&7)>>1
//   f4 = ((wr*KST + k)*2 + i)*32 + gid*4 + tig ;  word = f4*4 + khalf*2 + hi
// B word for (kk, kk+1, col n), kk even:
//   k=kk>>4, khalf=(kk&15)>>3, tig=((kk&15)&7)>>1
//   wcol=n>>6, j=(n>>3)&7, g=j>>1, jpar=j&1, gid=n&7
//   f4 = wcol*(KST*128) + k*128 + g*32 + gid*4 + tig ; word = f4*4 + jpar*2 + khalf
// ---------------------------------------------------------------------------
__device__ __forceinline__ int aword(int row, int c, int kst) {
    int f4 = (((row >> 5) * kst + (c >> 4)) * 2 + ((row >> 4) & 1)) * 32
           + (row & 7) * 4 + (((c & 15) & 7) >> 1);
    return f4 * 4 + ((c & 15) >> 3) * 2 + ((row >> 3) & 1);
}
__device__ __forceinline__ int bword(int kk, int n, int kst) {
    int f4 = (n >> 6) * (kst * 128) + (kk >> 4) * 128 + (((n >> 3) & 7) >> 1) * 32
           + (n & 7) * 4 + (((kk & 15) & 7) >> 1);
    return f4 * 4 + ((n >> 3) & 1) * 2 + ((kk & 15) >> 3);
}

// 128x128xK fp16 tile GEMM from fragment-major tiles. 8 warps 4(m)x2(n).
template <int KST>
__device__ __forceinline__ void gemmH(const float* __restrict__ Af,
                                      const float* __restrict__ Bf,
                                      float C[2][8][4], int htid) {
    const int lane = htid & 31, warp = htid >> 5;
    const float4* A4 = (const float4*)Af + (warp >> 1) * (KST * 64) + lane;
    const float4* B4 = (const float4*)Bf + (warp & 1) * (KST * 128) + lane;
#pragma unroll
    for (int k = 0; k < KST; ++k) {
        float4 fa0 = A4[k * 64];
        float4 fa1 = A4[k * 64 + 32];
        uint32_t a[2][4] = {
            {__float_as_uint(fa0.x), __float_as_uint(fa0.y), __float_as_uint(fa0.z), __float_as_uint(fa0.w)},
            {__float_as_uint(fa1.x), __float_as_uint(fa1.y), __float_as_uint(fa1.z), __float_as_uint(fa1.w)}};
        uint32_t b[8][2];
#pragma unroll
        for (int g = 0; g < 4; ++g) {
            float4 fb = B4[k * 128 + g * 32];
            b[2 * g][0] = __float_as_uint(fb.x);
            b[2 * g][1] = __float_as_uint(fb.y);
            b[2 * g + 1][0] = __float_as_uint(fb.z);
            b[2 * g + 1][1] = __float_as_uint(fb.w);
        }
#pragma unroll
        for (int i = 0; i < 2; ++i)
#pragma unroll
            for (int j = 0; j < 8; ++j) mma16(C[i][j], a[i], b[j]);
    }
}

// smem float offsets for k_pair (fp16 tiles)
#define OFF_BF2  0        // W_f2 fp16 frags: 2048 f4 = 8192 floats
#define OFF_BF1  8192     // W_f1 fp16 frags: 512 f4 = 2048 floats
#define OFF_BB1  10240
#define OFF_BB2  10368
#define OFF_UNI0 10496
#define UNI_W    16896    // union: A2 fp16 frags (8192 f) or w rows [128][132] fp32
#define HALF_STRIDE (UNI_W + 128)  // + scut
#define SMEM_PAIR_F (OFF_UNI0 + 2 * HALF_STRIDE)  // 44544 f = 178176 B

// classic strided-smem tf32 GEMM for k_proj / k_out
template <int KSTEPS, int ASTRIDE, int BSTRIDE>
__device__ __forceinline__ void gemm128(const float* __restrict__ As,
                                        const float* __restrict__ Bs,
                                        float C[2][8][4], int tid) {
    const int lane = tid & 31, warp = tid >> 5;
    const int wm = (warp >> 1) * 32, wn = (warp & 1) * 64;
    const int gid = lane >> 2, tig = lane & 3;
#pragma unroll
    for (int k = 0; k < KSTEPS; ++k) {
        uint32_t a[2][4];
#pragma unroll
        for (int i = 0; i < 2; ++i) {
            const float* ap = As + (wm + i * 16 + gid) * ASTRIDE + k * 8 + tig;
            a[i][0] = __float_as_uint(ap[0]);
            a[i][1] = __float_as_uint(ap[8 * ASTRIDE]);
            a[i][2] = __float_as_uint(ap[4]);
            a[i][3] = __float_as_uint(ap[8 * ASTRIDE + 4]);
        }
        uint32_t b[8][2];
#pragma unroll
        for (int j = 0; j < 8; ++j) {
            const float* bp = Bs + (k * 8 + tig) * BSTRIDE + wn + j * 8 + gid;
            b[j][0] = __float_as_uint(bp[0]);
            b[j][1] = __float_as_uint(bp[4 * BSTRIDE]);
        }
#pragma unroll
        for (int i = 0; i < 2; ++i)
#pragma unroll
            for (int j = 0; j < 8; ++j) mma8(C[i][j], a[i], b[j]);
    }
}

// ---------------------------------------------------------------------------
// bucketing
// ---------------------------------------------------------------------------
__global__ void k_czero() {
    int i = blockIdx.x * blockDim.x + threadIdx.x;
    if (i < N_ATOMS) g_cnt[i] = 0;
}
__global__ void k_bucket(const int* __restrict__ pidx) {
    int p = blockIdx.x * blockDim.x + threadIdx.x;
    if (p < N_PAIRS) {
        int i = __ldg(&pidx[p]);
        int j = __ldg(&pidx[N_PAIRS + p]);
        int slot = atomicAdd(&g_cnt[i], 1);
        if (slot < CAP) g_bucket[(size_t)i * CAP + slot] = make_int2(p, j);
    }
}

// ---------------------------------------------------------------------------
// x = atomic_embedding @ W_in -> g_x
// ---------------------------------------------------------------------------
__global__ __launch_bounds__(256, 1) void k_proj(const float* __restrict__ emb,
                                                 const float* __restrict__ W_in) {
    extern __shared__ float smem[];
    float* As = smem;
    float* Bs = smem + 128 * 132;
    const int tid = threadIdx.x;
    const int r0 = blockIdx.x * 128;
    for (int t = tid; t < 128 * 132; t += 256) {
        int r = t / 132, c = t % 132;
        float v = 0.f;
        if (c < 128 && (r0 + r) < N_ATOMS) v = emb[(size_t)(r0 + r) * 128 + c];
        As[t] = tf32f(v);
    }
    for (int t = tid; t < 128 * 136; t += 256) {
        int r = t / 136, c = t % 136;
        Bs[t] = (c < 128) ? tf32f(W_in[r * 128 + c]) : 0.f;
    }
    __syncthreads();
    float C[2][8][4] = {};
    gemm128<16, 132, 136>(As, Bs, C, tid);
    const int lane = tid & 31, warp = tid >> 5;
    const int wm = (warp >> 1) * 32, wn = (warp & 1) * 64;
    const int gid = lane >> 2, tig = lane & 3;
#pragma unroll
    for (int i = 0; i < 2; ++i)
#pragma unroll
        for (int h = 0; h < 2; ++h) {
            int row = r0 + wm + i * 16 + gid + h * 8;
            if (row < N_ATOMS)
#pragma unroll
                for (int j = 0; j < 8; ++j) {
                    int col = wn + j * 8 + 2 * tig;
                    float2 v = make_float2(C[i][j][h * 2], C[i][j][h * 2 + 1]);
                    *reinterpret_cast<float2*>(&g_x[(size_t)row * 128 + col]) = v;
                }
        }
}

// ---------------------------------------------------------------------------
// Phase A: persistent filter-network GEMMs (fp16 mma); staged fp32 w write.
// 512 threads = two independent 256-thread halves; weights shared in smem.
// ---------------------------------------------------------------------------
__global__ __launch_bounds__(512, 1)
void k_pair(const float* __restrict__ f_ij, const float* __restrict__ cut,
            const float* __restrict__ W_f1, const float* __restrict__ b_f1,
            const float* __restrict__ W_f2, const float* __restrict__ b_f2,
            int tile_base, int tile_count) {
    extern __shared__ float smem[];
    const int tid = threadIdx.x;
    const int half = tid >> 8;
    const int htid = tid & 255;

    float* Bf2 = smem + OFF_BF2;
    float* Bf1 = smem + OFF_BF1;
    float* uni = smem + OFF_UNI0 + half * HALF_STRIDE;
    float* scut = uni + UNI_W;
    uint32_t* uw = (uint32_t*)uni;

    // one-time: pack weights to fp16 fragment-major
    for (int t = tid; t < 64 * 128; t += 512) {     // W_f2: 64 kk-pairs x 128 n
        int kk = (t >> 7) * 2, n = t & 127;
        ((uint32_t*)Bf2)[bword(kk, n, 8)] =
            packh2(W_f2[kk * 128 + n], W_f2[(kk + 1) * 128 + n]);
    }
    for (int t = tid; t < 16 * 128; t += 512) {     // W_f1: 16 kk-pairs x 128 n (pad>=20 -> 0)
        int kk = (t >> 7) * 2, n = t & 127;
        float v0 = (kk < 20) ? W_f1[kk * 128 + n] : 0.f;
        float v1 = (kk + 1 < 20) ? W_f1[(kk + 1) * 128 + n] : 0.f;
        ((uint32_t*)Bf1)[bword(kk, n, 2)] = packh2(v0, v1);
    }
    if (tid < 128) smem[OFF_BB1 + tid] = b_f1[tid];
    else if (tid < 256) smem[OFF_BB2 + tid - 128] = b_f2[tid - 128];
    __syncthreads();

    const float* b1s = smem + OFF_BB1;
    const float* b2s = smem + OFF_BB2;
    const int bar = 1 + half;
    const int lane = htid & 31, warp = htid >> 5;
    const int wm = (warp >> 1) * 32, wn = (warp & 1) * 64;
    const int gid = lane >> 2, tig = lane & 3;

    const int end = tile_base + tile_count;
    const int step = (int)gridDim.x * 2;
    int tile = tile_base + (int)blockIdx.x * 2 + half;
    if (tile >= end) return;

    const int prow = htid >> 1;
    const int podd = htid & 1;
    const int pcol = podd * 10;
    float pf[10];
    float pcut = 0.f;
    {
        const float* src = f_ij + (size_t)(tile * 128 + prow) * 20 + pcol;
#pragma unroll
        for (int q = 0; q < 10; ++q) pf[q] = __ldg(src + q);
        if (htid < 128) pcut = __ldg(&cut[tile * 128 + htid]);
    }

    // S3 writer base: own-lane float4 at (wr, k0=wn>>4, i=0)
    float4* A2v = (float4*)uni + (((warp >> 1) * 8 + (wn >> 4)) * 2) * 32 + lane;

    for (; tile < end; tile += step) {
        const int p0 = tile * 128;

        // S1: prefetched f_ij -> fp16 fragment words (full coverage incl. pad)
        if (!podd) {
#pragma unroll
            for (int q = 0; q < 5; ++q)
                uw[aword(prow, 2 * q * 1 + 0 + 0 + (q * 2), 2) * 0 + aword(prow, q * 2, 2)] =
                    packh2(pf[2 * q], pf[2 * q + 1]);
        } else {
#pragma unroll
            for (int q = 0; q < 5; ++q)
                uw[aword(prow, 10 + q * 2, 2)] = packh2(pf[2 * q], pf[2 * q + 1]);
#pragma unroll
            for (int q = 0; q < 6; ++q)
                uw[aword(prow, 20 + q * 2, 2)] = 0u;
        }
        if (htid < 128) scut[htid] = pcut;
        barh(bar);

        // prefetch next tile
        int nt = tile + step;
        if (nt < end) {
            const float* src = f_ij + (size_t)(nt * 128 + prow) * 20 + pcol;
#pragma unroll
            for (int q = 0; q < 10; ++q) pf[q] = __ldg(src + q);
            if (htid < 128) pcut = __ldg(&cut[nt * 128 + htid]);
        }

        // GEMM1 (K=32 incl pad -> 2 ksteps, fp16)
        float C[2][8][4] = {};
        gemmH<2>(uni, Bf1, C, htid);
        barh(bar);

        // S3: hidden = fp16(fssp(C+b1)) -> A2 fragments; full float4 per thread, no shuffles
#pragma unroll
        for (int i = 0; i < 2; ++i) {
#pragma unroll
            for (int q = 0; q < 4; ++q) {
                int c0 = wn + q * 16 + 2 * tig;      // j = 2q
                int c1 = c0 + 8;                      // j = 2q+1
                float4 o;
                o.x = __uint_as_float(packh2(fssp(C[i][2 * q][0] + b1s[c0]),
                                             fssp(C[i][2 * q][1] + b1s[c0 + 1])));
                o.y = __uint_as_float(packh2(fssp(C[i][2 * q][2] + b1s[c0]),
                                             fssp(C[i][2 * q][3] + b1s[c0 + 1])));
                o.z = __uint_as_float(packh2(fssp(C[i][2 * q + 1][0] + b1s[c1]),
                                             fssp(C[i][2 * q + 1][1] + b1s[c1 + 1])));
                o.w = __uint_as_float(packh2(fssp(C[i][2 * q + 1][2] + b1s[c1]),
                                             fssp(C[i][2 * q + 1][3] + b1s[c1 + 1])));
                A2v[(q * 2 + i) * 32] = o;
            }
        }
        barh(bar);

        // GEMM2 (K=128 -> 8 ksteps, fp16)
        float C2[2][8][4] = {};
        gemmH<8>(uni, Bf2, C2, htid);
        barh(bar);  // A2 reads done before w-stage overwrites union

        // stage w = (C2+b2)*cut rows fp32 (stride 132)
#pragma unroll
        for (int i = 0; i < 2; ++i)
#pragma unroll
            for (int h = 0; h < 2; ++h) {
                int r = wm + i * 16 + gid + h * 8;
                float ct = scut[r];
#pragma unroll
                for (int j = 0; j < 8; ++j) {
                    int col = wn + j * 8 + 2 * tig;
                    float2 v = make_float2((C2[i][j][h * 2] + b2s[col]) * ct,
                                           (C2[i][j][h * 2 + 1] + b2s[col + 1]) * ct);
                    *reinterpret_cast<float2*>(&uni[r * 132 + col]) = v;
                }
            }
        barh(bar);

        // coalesced fp32 write-out: warp = full 512B rows
#pragma unroll
        for (int rr = 0; rr < 16; ++rr) {
            int row = warp * 16 + rr;
            float4 v = *reinterpret_cast<const float4*>(uni + row * 132 + lane * 4);
            ((float4*)(g_w + (size_t)(p0 + row) * 128))[lane] = v;
        }
        barh(bar);  // w reads done before next S1 overwrite
    }
}

// ---------------------------------------------------------------------------
// Phase B: one warp per atom sums w[p] * x[j], unrolled x2 for MLP
// ---------------------------------------------------------------------------
__global__ __launch_bounds__(256, 2) void k_gather() {
    int atom = (blockIdx.x * 256 + threadIdx.x) >> 5;
    int lane = threadIdx.x & 31;
    if (atom >= N_ATOMS) return;
    int cnt = __ldg(&g_cnt[atom]);
    if (cnt > CAP) cnt = CAP;
    const int2* bucket = g_bucket + (size_t)atom * CAP;
    float4 acc = make_float4(0.f, 0.f, 0.f, 0.f);

    int t = 0;
    for (; t + 2 <= cnt; t += 2) {
        int2 e0 = __ldg(&bucket[t]);
        int2 e1 = __ldg(&bucket[t + 1]);
        float4 w0 = __ldg((const float4*)(g_w + (size_t)e0.x * 128) + lane);
        float4 x0 = __ldg((const float4*)(g_x + (size_t)e0.y * 128) + lane);
        float4 w1 = __ldg((const float4*)(g_w + (size_t)e1.x * 128) + lane);
        float4 x1 = __ldg((const float4*)(g_x + (size_t)e1.y * 128) + lane);
        acc.x += w0.x * x0.x; acc.y += w0.y * x0.y;
        acc.z += w0.z * x0.z; acc.w += w0.w * x0.w;
        acc.x += w1.x * x1.x; acc.y += w1.y * x1.y;
        acc.z += w1.z * x1.z; acc.w += w1.w * x1.w;
    }
    if (t < cnt) {
        int2 e = __ldg(&bucket[t]);
        float4 w = __ldg((const float4*)(g_w + (size_t)e.x * 128) + lane);
        float4 x = __ldg((const float4*)(g_x + (size_t)e.y * 128) + lane);
        acc.x += w.x * x.x; acc.y += w.y * x.y;
        acc.z += w.z * x.z; acc.w += w.w * x.w;
    }
    *((float4*)(g_acc + (size_t)atom * 128) + lane) = acc;
}

// ---------------------------------------------------------------------------
// Output MLP
// ---------------------------------------------------------------------------
__global__ __launch_bounds__(256, 1) void k_out(const float* __restrict__ W_o1,
                                                const float* __restrict__ b_o1,
                                                const float* __restrict__ W_o2,
                                                const float* __restrict__ b_o2,
                                                float* __restrict__ out) {
    extern __shared__ float smem[];
    float* As = smem;
    float* Bs = smem + 128 * 132;
    float* sbv = Bs + 128 * 136;
    const int tid = threadIdx.x;
    const int r0 = blockIdx.x * 128;
    for (int t = tid; t < 128 * 132; t += 256) {
        int r = t / 132, c = t % 132;
        float v = 0.f;
        if (c < 128 && (r0 + r) < N_ATOMS) v = g_acc[(size_t)(r0 + r) * 128 + c];
        As[t] = tf32f(v);
    }
    for (int t = tid; t < 128 * 136; t += 256) {
        int r = t / 136, c = t % 136;
        Bs[t] = (c < 128) ? tf32f(W_o1[r * 128 + c]) : 0.f;
    }
    if (tid < 128) sbv[tid] = b_o1[tid];
    __syncthreads();
    float C[2][8][4] = {};
    gemm128<16, 132, 136>(As, Bs, C, tid);
    __syncthreads();
    const int lane = tid & 31, warp = tid >> 5;
    const int wm = (warp >> 1) * 32, wn = (warp & 1) * 64;
    const int gid = lane >> 2, tig = lane & 3;
#pragma unroll
    for (int i = 0; i < 2; ++i) {
        int r = wm + i * 16 + gid;
#pragma unroll
        for (int j = 0; j < 8; ++j) {
            int col = wn + j * 8 + 2 * tig;
            As[r * 132 + col]           = tf32f(fssp(C[i][j][0] + sbv[col]));
            As[r * 132 + col + 1]       = tf32f(fssp(C[i][j][1] + sbv[col + 1]));
            As[(r + 8) * 132 + col]     = tf32f(fssp(C[i][j][2] + sbv[col]));
            As[(r + 8) * 132 + col + 1] = tf32f(fssp(C[i][j][3] + sbv[col + 1]));
        }
    }
    for (int t = tid; t < 128 * 136; t += 256) {
        int r = t / 136, c = t % 136;
        Bs[t] = (c < 128) ? tf32f(W_o2[r * 128 + c]) : 0.f;
    }
    if (tid < 128) sbv[tid] = b_o2[tid];
    __syncthreads();
    float C2[2][8][4] = {};
    gemm128<16, 132, 136>(As, Bs, C2, tid);
#pragma unroll
    for (int i = 0; i < 2; ++i)
#pragma unroll
        for (int h = 0; h < 2; ++h) {
            int row = r0 + wm + i * 16 + gid + h * 8;
            if (row < N_ATOMS)
#pragma unroll
                for (int j = 0; j < 8; ++j) {
                    int col = wn + j * 8 + 2 * tig;
                    float2 v = make_float2(C2[i][j][h * 2] + sbv[col],
                                           C2[i][j][h * 2 + 1] + sbv[col + 1]);
                    *reinterpret_cast<float2*>(&out[(size_t)row * 128 + col]) = v;
                }
        }
}

extern "C" void kernel_launch(void* const* d_in, const int* in_sizes, int n_in,
                              void* d_out, int out_size) {
    const float* emb  = (const float*)d_in[0];
    const int*   pidx = (const int*)d_in[1];
    const float* fij  = (const float*)d_in[2];
    const float* cut  = (const float*)d_in[3];
    const float* W_in = (const float*)d_in[4];
    const float* W_f1 = (const float*)d_in[5];
    const float* b_f1 = (const float*)d_in[6];
    const float* W_f2 = (const float*)d_in[7];
    const float* b_f2 = (const float*)d_in[8];
    const float* W_o1 = (const float*)d_in[9];
    const float* b_o1 = (const float*)d_in[10];
    const float* W_o2 = (const float*)d_in[11];
    const float* b_o2 = (const float*)d_in[12];
    float* out = (float*)d_out;

    const int smemPair = SMEM_PAIR_F * 4;  // 178176 B
    const int smemGemm = (128 * 132 + 128 * 136 + 128) * 4;

    cudaFuncSetAttribute(k_pair, cudaFuncAttributeMaxDynamicSharedMemorySize, smemPair);
    cudaFuncSetAttribute(k_proj, cudaFuncAttributeMaxDynamicSharedMemorySize, smemGemm);
    cudaFuncSetAttribute(k_out,  cudaFuncAttributeMaxDynamicSharedMemorySize, smemGemm);

    const int NT = N_PAIRS / 128;  // 12500
    k_czero<<<(N_ATOMS + 255) / 256, 256>>>();
    k_bucket<<<(N_PAIRS + 255) / 256, 256>>>(pidx);
    k_proj<<<(N_ATOMS + 127) / 128, 256, smemGemm>>>(emb, W_in);
    k_pair<<<148, 512, smemPair>>>(fij, cut, W_f1, b_f1, W_f2, b_f2, 0, NT / 2);
    k_pair<<<148, 512, smemPair>>>(fij, cut, W_f1, b_f1, W_f2, b_f2, NT / 2, NT - NT / 2);
    k_gather<<<(N_ATOMS * 32 + 255) / 256, 256>>>();
    k_out<<<(N_ATOMS + 127) / 128, 256, smemGemm>>>(W_o1, b_o1, W_o2, b_o2, out);
}

// round 13
// speedup vs baseline: 2.1392x; 1.1680x over previous
#include <cuda_runtime.h>
#include <cuda_fp16.h>
#include <cstdint>

#define N_ATOMS 50000
#define N_PAIRS 1600000
#define LN2F 0.6931471805599453f
#define CAP 96

__device__ float g_x[(size_t)N_ATOMS * 128];
__device__ float g_acc[(size_t)N_ATOMS * 128];
__device__ __half g_wh[(size_t)N_PAIRS * 128];   // cutoff-weighted filters (fp16 storage)
__device__ int   g_cnt[N_ATOMS];
__device__ int2  g_bucket[(size_t)N_ATOMS * CAP];

// ---------------------------------------------------------------------------
// helpers
// ---------------------------------------------------------------------------
__device__ __forceinline__ uint32_t f2tf32(float x) {
    uint32_t u; asm("cvt.rna.tf32.f32 %0, %1;" : "=r"(u) : "f"(x)); return u;
}
__device__ __forceinline__ float tf32f(float x) { return __uint_as_float(f2tf32(x)); }

__device__ __forceinline__ float fssp(float x) {
    if (x > 60.f) return x - LN2F;
    float t, l;
    asm("ex2.approx.f32 %0, %1;" : "=f"(t) : "f"(x * 1.4426950408889634f));
    asm("lg2.approx.f32 %0, %1;" : "=f"(l) : "f"(t + 1.0f));
    return 0.69314718055994531f * (l - 1.0f);
}
__device__ __forceinline__ void barh(int id) {
    asm volatile("bar.sync %0, 256;" :: "r"(id) : "memory");
}
__device__ __forceinline__ uint32_t packh2(float a, float b) {
    __half2 h = __floats2half2_rn(a, b);
    return *reinterpret_cast<uint32_t*>(&h);
}
__device__ __forceinline__ float2 unpackh2(uint32_t u) {
    __half2 h = *reinterpret_cast<__half2*>(&u);
    return __half22float2(h);
}
// tf32 mma (k_proj / k_out)
__device__ __forceinline__ void mma8(float c[4], const uint32_t a[4], const uint32_t b[2]) {
    asm volatile(
        "mma.sync.aligned.m16n8k8.row.col.f32.tf32.tf32.f32 "
        "{%0,%1,%2,%3}, {%4,%5,%6,%7}, {%8,%9}, {%0,%1,%2,%3};\n"
        : "+f"(c[0]), "+f"(c[1]), "+f"(c[2]), "+f"(c[3])
        : "r"(a[0]), "r"(a[1]), "r"(a[2]), "r"(a[3]), "r"(b[0]), "r"(b[1]));
}
// fp16 mma (k_pair)
__device__ __forceinline__ void mma16(float c[4], const uint32_t a[4], const uint32_t b[2]) {
    asm volatile(
        "mma.sync.aligned.m16n8k16.row.col.f32.f16.f16.f32 "
        "{%0,%1,%2,%3}, {%4,%5,%6,%7}, {%8,%9}, {%0,%1,%2,%3};\n"
        : "+f"(c[0]), "+f"(c[1]), "+f"(c[2]), "+f"(c[3])
        : "r"(a[0]), "r"(a[1]), "r"(a[2]), "r"(a[3]), "r"(b[0]), "r"(b[1]));
}

// ---------------------------------------------------------------------------
// fp16 fragment-major word indexing (m16n8k16) — validated round 12
// ---------------------------------------------------------------------------
__device__ __forceinline__ int aword(int row, int c, int kst) {
    int f4 = (((row >> 5) * kst + (c >> 4)) * 2 + ((row >> 4) & 1)) * 32
           + (row & 7) * 4 + (((c & 15) & 7) >> 1);
    return f4 * 4 + ((c & 15) >> 3) * 2 + ((row >> 3) & 1);
}
__device__ __forceinline__ int bword(int kk, int n, int kst) {
    int f4 = (n >> 6) * (kst * 128) + (kk >> 4) * 128 + (((n >> 3) & 7) >> 1) * 32
           + (n & 7) * 4 + (((kk & 15) & 7) >> 1);
    return f4 * 4 + ((n >> 3) & 1) * 2 + ((kk & 15) >> 3);
}

// 128x128xK fp16 tile GEMM from fragment-major tiles. 8 warps 4(m)x2(n).
template <int KST>
__device__ __forceinline__ void gemmH(const float* __restrict__ Af,
                                      const float* __restrict__ Bf,
                                      float C[2][8][4], int htid) {
    const int lane = htid & 31, warp = htid >> 5;
    const float4* A4 = (const float4*)Af + (warp >> 1) * (KST * 64) + lane;
    const float4* B4 = (const float4*)Bf + (warp & 1) * (KST * 128) + lane;
#pragma unroll
    for (int k = 0; k < KST; ++k) {
        float4 fa0 = A4[k * 64];
        float4 fa1 = A4[k * 64 + 32];
        uint32_t a[2][4] = {
            {__float_as_uint(fa0.x), __float_as_uint(fa0.y), __float_as_uint(fa0.z), __float_as_uint(fa0.w)},
            {__float_as_uint(fa1.x), __float_as_uint(fa1.y), __float_as_uint(fa1.z), __float_as_uint(fa1.w)}};
        uint32_t b[8][2];
#pragma unroll
        for (int g = 0; g < 4; ++g) {
            float4 fb = B4[k * 128 + g * 32];
            b[2 * g][0] = __float_as_uint(fb.x);
            b[2 * g][1] = __float_as_uint(fb.y);
            b[2 * g + 1][0] = __float_as_uint(fb.z);
            b[2 * g + 1][1] = __float_as_uint(fb.w);
        }
#pragma unroll
        for (int i = 0; i < 2; ++i)
#pragma unroll
            for (int j = 0; j < 8; ++j) mma16(C[i][j], a[i], b[j]);
    }
}

// smem float offsets for k_pair (fp16 tiles, fp16 w-stage)
#define OFF_BF2  0        // W_f2 fp16 frags: 8192 floats
#define OFF_BF1  8192     // W_f1 fp16 frags: 2048 floats
#define OFF_BB1  10240
#define OFF_BB2  10368
#define OFF_UNI0 10496
#define UNI_W    8704     // union: A2 frags (8192 f) or w h2-rows [128][68] u32
#define HALF_STRIDE (UNI_W + 128)  // + scut
#define SMEM_PAIR_F (OFF_UNI0 + 2 * HALF_STRIDE)  // 28160 f = 112640 B

// classic strided-smem tf32 GEMM for k_proj / k_out
template <int KSTEPS, int ASTRIDE, int BSTRIDE>
__device__ __forceinline__ void gemm128(const float* __restrict__ As,
                                        const float* __restrict__ Bs,
                                        float C[2][8][4], int tid) {
    const int lane = tid & 31, warp = tid >> 5;
    const int wm = (warp >> 1) * 32, wn = (warp & 1) * 64;
    const int gid = lane >> 2, tig = lane & 3;
#pragma unroll
    for (int k = 0; k < KSTEPS; ++k) {
        uint32_t a[2][4];
#pragma unroll
        for (int i = 0; i < 2; ++i) {
            const float* ap = As + (wm + i * 16 + gid) * ASTRIDE + k * 8 + tig;
            a[i][0] = __float_as_uint(ap[0]);
            a[i][1] = __float_as_uint(ap[8 * ASTRIDE]);
            a[i][2] = __float_as_uint(ap[4]);
            a[i][3] = __float_as_uint(ap[8 * ASTRIDE + 4]);
        }
        uint32_t b[8][2];
#pragma unroll
        for (int j = 0; j < 8; ++j) {
            const float* bp = Bs + (k * 8 + tig) * BSTRIDE + wn + j * 8 + gid;
            b[j][0] = __float_as_uint(bp[0]);
            b[j][1] = __float_as_uint(bp[4 * BSTRIDE]);
        }
#pragma unroll
        for (int i = 0; i < 2; ++i)
#pragma unroll
            for (int j = 0; j < 8; ++j) mma8(C[i][j], a[i], b[j]);
    }
}

// ---------------------------------------------------------------------------
// bucketing
// ---------------------------------------------------------------------------
__global__ void k_czero() {
    int i = blockIdx.x * blockDim.x + threadIdx.x;
    if (i < N_ATOMS) g_cnt[i] = 0;
}
__global__ void k_bucket(const int* __restrict__ pidx) {
    int p = blockIdx.x * blockDim.x + threadIdx.x;
    if (p < N_PAIRS) {
        int i = __ldg(&pidx[p]);
        int j = __ldg(&pidx[N_PAIRS + p]);
        int slot = atomicAdd(&g_cnt[i], 1);
        if (slot < CAP) g_bucket[(size_t)i * CAP + slot] = make_int2(p, j);
    }
}

// ---------------------------------------------------------------------------
// x = atomic_embedding @ W_in -> g_x
// ---------------------------------------------------------------------------
__global__ __launch_bounds__(256, 1) void k_proj(const float* __restrict__ emb,
                                                 const float* __restrict__ W_in) {
    extern __shared__ float smem[];
    float* As = smem;
    float* Bs = smem + 128 * 132;
    const int tid = threadIdx.x;
    const int r0 = blockIdx.x * 128;
    for (int t = tid; t < 128 * 132; t += 256) {
        int r = t / 132, c = t % 132;
        float v = 0.f;
        if (c < 128 && (r0 + r) < N_ATOMS) v = emb[(size_t)(r0 + r) * 128 + c];
        As[t] = tf32f(v);
    }
    for (int t = tid; t < 128 * 136; t += 256) {
        int r = t / 136, c = t % 136;
        Bs[t] = (c < 128) ? tf32f(W_in[r * 128 + c]) : 0.f;
    }
    __syncthreads();
    float C[2][8][4] = {};
    gemm128<16, 132, 136>(As, Bs, C, tid);
    const int lane = tid & 31, warp = tid >> 5;
    const int wm = (warp >> 1) * 32, wn = (warp & 1) * 64;
    const int gid = lane >> 2, tig = lane & 3;
#pragma unroll
    for (int i = 0; i < 2; ++i)
#pragma unroll
        for (int h = 0; h < 2; ++h) {
            int row = r0 + wm + i * 16 + gid + h * 8;
            if (row < N_ATOMS)
#pragma unroll
                for (int j = 0; j < 8; ++j) {
                    int col = wn + j * 8 + 2 * tig;
                    float2 v = make_float2(C[i][j][h * 2], C[i][j][h * 2 + 1]);
                    *reinterpret_cast<float2*>(&g_x[(size_t)row * 128 + col]) = v;
                }
        }
}

// ---------------------------------------------------------------------------
// Phase A: persistent filter-network GEMMs (fp16 mma); staged fp16 w write.
// ---------------------------------------------------------------------------
__global__ __launch_bounds__(512, 1)
void k_pair(const float* __restrict__ f_ij, const float* __restrict__ cut,
            const float* __restrict__ W_f1, const float* __restrict__ b_f1,
            const float* __restrict__ W_f2, const float* __restrict__ b_f2,
            int tile_base, int tile_count) {
    extern __shared__ float smem[];
    const int tid = threadIdx.x;
    const int half = tid >> 8;
    const int htid = tid & 255;

    float* Bf2 = smem + OFF_BF2;
    float* Bf1 = smem + OFF_BF1;
    float* uni = smem + OFF_UNI0 + half * HALF_STRIDE;
    float* scut = uni + UNI_W;
    uint32_t* uw = (uint32_t*)uni;

    // one-time: pack weights to fp16 fragment-major
    for (int t = tid; t < 64 * 128; t += 512) {
        int kk = (t >> 7) * 2, n = t & 127;
        ((uint32_t*)Bf2)[bword(kk, n, 8)] =
            packh2(W_f2[kk * 128 + n], W_f2[(kk + 1) * 128 + n]);
    }
    for (int t = tid; t < 16 * 128; t += 512) {
        int kk = (t >> 7) * 2, n = t & 127;
        float v0 = (kk < 20) ? W_f1[kk * 128 + n] : 0.f;
        float v1 = (kk + 1 < 20) ? W_f1[(kk + 1) * 128 + n] : 0.f;
        ((uint32_t*)Bf1)[bword(kk, n, 2)] = packh2(v0, v1);
    }
    if (tid < 128) smem[OFF_BB1 + tid] = b_f1[tid];
    else if (tid < 256) smem[OFF_BB2 + tid - 128] = b_f2[tid - 128];
    __syncthreads();

    const float* b1s = smem + OFF_BB1;
    const float* b2s = smem + OFF_BB2;
    const int bar = 1 + half;
    const int lane = htid & 31, warp = htid >> 5;
    const int wm = (warp >> 1) * 32, wn = (warp & 1) * 64;
    const int gid = lane >> 2, tig = lane & 3;

    const int end = tile_base + tile_count;
    const int step = (int)gridDim.x * 2;
    int tile = tile_base + (int)blockIdx.x * 2 + half;
    if (tile >= end) return;

    const int prow = htid >> 1;
    const int podd = htid & 1;
    const int pcol = podd * 10;
    float pf[10];
    float pcut = 0.f;
    {
        const float* src = f_ij + (size_t)(tile * 128 + prow) * 20 + pcol;
#pragma unroll
        for (int q = 0; q < 10; ++q) pf[q] = __ldg(src + q);
        if (htid < 128) pcut = __ldg(&cut[tile * 128 + htid]);
    }

    // S3 writer base: own-lane float4 at (wr, k0=wn>>4, i=0)
    float4* A2v = (float4*)uni + (((warp >> 1) * 8 + (wn >> 4)) * 2) * 32 + lane;

    for (; tile < end; tile += step) {
        const int p0 = tile * 128;

        // S1: prefetched f_ij -> fp16 fragment words (incl. zero pad)
        if (!podd) {
#pragma unroll
            for (int q = 0; q < 5; ++q)
                uw[aword(prow, q * 2, 2)] = packh2(pf[2 * q], pf[2 * q + 1]);
        } else {
#pragma unroll
            for (int q = 0; q < 5; ++q)
                uw[aword(prow, 10 + q * 2, 2)] = packh2(pf[2 * q], pf[2 * q + 1]);
#pragma unroll
            for (int q = 0; q < 6; ++q)
                uw[aword(prow, 20 + q * 2, 2)] = 0u;
        }
        if (htid < 128) scut[htid] = pcut;
        barh(bar);

        // prefetch next tile
        int nt = tile + step;
        if (nt < end) {
            const float* src = f_ij + (size_t)(nt * 128 + prow) * 20 + pcol;
#pragma unroll
            for (int q = 0; q < 10; ++q) pf[q] = __ldg(src + q);
            if (htid < 128) pcut = __ldg(&cut[nt * 128 + htid]);
        }

        // GEMM1 (K=32 incl pad -> 2 ksteps, fp16)
        float C[2][8][4] = {};
        gemmH<2>(uni, Bf1, C, htid);
        barh(bar);

        // S3: hidden = fp16(fssp(C+b1)) -> A2 fragments; full float4/thread
#pragma unroll
        for (int i = 0; i < 2; ++i) {
#pragma unroll
            for (int q = 0; q < 4; ++q) {
                int c0 = wn + q * 16 + 2 * tig;
                int c1 = c0 + 8;
                float4 o;
                o.x = __uint_as_float(packh2(fssp(C[i][2 * q][0] + b1s[c0]),
                                             fssp(C[i][2 * q][1] + b1s[c0 + 1])));
                o.y = __uint_as_float(packh2(fssp(C[i][2 * q][2] + b1s[c0]),
                                             fssp(C[i][2 * q][3] + b1s[c0 + 1])));
                o.z = __uint_as_float(packh2(fssp(C[i][2 * q + 1][0] + b1s[c1]),
                                             fssp(C[i][2 * q + 1][1] + b1s[c1 + 1])));
                o.w = __uint_as_float(packh2(fssp(C[i][2 * q + 1][2] + b1s[c1]),
                                             fssp(C[i][2 * q + 1][3] + b1s[c1 + 1])));
                A2v[(q * 2 + i) * 32] = o;
            }
        }
        barh(bar);

        // GEMM2 (K=128 -> 8 ksteps, fp16)
        float C2[2][8][4] = {};
        gemmH<8>(uni, Bf2, C2, htid);
        barh(bar);  // A2 reads done before w-stage overwrites union

        // stage w = fp16((C2+b2)*cut) as h2 words, rows stride 68 (conflict-free)
#pragma unroll
        for (int i = 0; i < 2; ++i)
#pragma unroll
            for (int h = 0; h < 2; ++h) {
                int r = wm + i * 16 + gid + h * 8;
                float ct = scut[r];
#pragma unroll
                for (int j = 0; j < 8; ++j) {
                    int c2 = (wn >> 1) + j * 4 + tig;  // h2-word column
                    uw[r * 68 + c2] = packh2((C2[i][j][h * 2] + b2s[2 * c2]) * ct,
                                             (C2[i][j][h * 2 + 1] + b2s[2 * c2 + 1]) * ct);
                }
            }
        barh(bar);

        // coalesced fp16 write-out: warp = full 256B rows
#pragma unroll
        for (int rr = 0; rr < 16; ++rr) {
            int row = warp * 16 + rr;
            uint2 v = make_uint2(uw[row * 68 + lane * 2], uw[row * 68 + lane * 2 + 1]);
            ((uint2*)(g_wh + (size_t)(p0 + row) * 128))[lane] = v;
        }
        barh(bar);  // w reads done before next S1 overwrite
    }
}

// ---------------------------------------------------------------------------
// Phase B: one warp per atom sums w[p] * x[j], unrolled x2 for MLP
// ---------------------------------------------------------------------------
__global__ __launch_bounds__(256, 2) void k_gather() {
    int atom = (blockIdx.x * 256 + threadIdx.x) >> 5;
    int lane = threadIdx.x & 31;
    if (atom >= N_ATOMS) return;
    int cnt = __ldg(&g_cnt[atom]);
    if (cnt > CAP) cnt = CAP;
    const int2* bucket = g_bucket + (size_t)atom * CAP;
    float4 acc = make_float4(0.f, 0.f, 0.f, 0.f);

    int t = 0;
    for (; t + 2 <= cnt; t += 2) {
        int2 e0 = __ldg(&bucket[t]);
        int2 e1 = __ldg(&bucket[t + 1]);
        uint2 w0 = __ldg((const uint2*)(g_wh + (size_t)e0.x * 128) + lane);
        float4 x0 = __ldg((const float4*)(g_x + (size_t)e0.y * 128) + lane);
        uint2 w1 = __ldg((const uint2*)(g_wh + (size_t)e1.x * 128) + lane);
        float4 x1 = __ldg((const float4*)(g_x + (size_t)e1.y * 128) + lane);
        float2 a0 = unpackh2(w0.x), b0 = unpackh2(w0.y);
        float2 a1 = unpackh2(w1.x), b1 = unpackh2(w1.y);
        acc.x += a0.x * x0.x; acc.y += a0.y * x0.y;
        acc.z += b0.x * x0.z; acc.w += b0.y * x0.w;
        acc.x += a1.x * x1.x; acc.y += a1.y * x1.y;
        acc.z += b1.x * x1.z; acc.w += b1.y * x1.w;
    }
    if (t < cnt) {
        int2 e = __ldg(&bucket[t]);
        uint2 w = __ldg((const uint2*)(g_wh + (size_t)e.x * 128) + lane);
        float4 x = __ldg((const float4*)(g_x + (size_t)e.y * 128) + lane);
        float2 a = unpackh2(w.x), b = unpackh2(w.y);
        acc.x += a.x * x.x; acc.y += a.y * x.y;
        acc.z += b.x * x.z; acc.w += b.y * x.w;
    }
    *((float4*)(g_acc + (size_t)atom * 128) + lane) = acc;
}

// ---------------------------------------------------------------------------
// Output MLP
// ---------------------------------------------------------------------------
__global__ __launch_bounds__(256, 1) void k_out(const float* __restrict__ W_o1,
                                                const float* __restrict__ b_o1,
                                                const float* __restrict__ W_o2,
                                                const float* __restrict__ b_o2,
                                                float* __restrict__ out) {
    extern __shared__ float smem[];
    float* As = smem;
    float* Bs = smem + 128 * 132;
    float* sbv = Bs + 128 * 136;
    const int tid = threadIdx.x;
    const int r0 = blockIdx.x * 128;
    for (int t = tid; t < 128 * 132; t += 256) {
        int r = t / 132, c = t % 132;
        float v = 0.f;
        if (c < 128 && (r0 + r) < N_ATOMS) v = g_acc[(size_t)(r0 + r) * 128 + c];
        As[t] = tf32f(v);
    }
    for (int t = tid; t < 128 * 136; t += 256) {
        int r = t / 136, c = t % 136;
        Bs[t] = (c < 128) ? tf32f(W_o1[r * 128 + c]) : 0.f;
    }
    if (tid < 128) sbv[tid] = b_o1[tid];
    __syncthreads();
    float C[2][8][4] = {};
    gemm128<16, 132, 136>(As, Bs, C, tid);
    __syncthreads();
    const int lane = tid & 31, warp = tid >> 5;
    const int wm = (warp >> 1) * 32, wn = (warp & 1) * 64;
    const int gid = lane >> 2, tig = lane & 3;
#pragma unroll
    for (int i = 0; i < 2; ++i) {
        int r = wm + i * 16 + gid;
#pragma unroll
        for (int j = 0; j < 8; ++j) {
            int col = wn + j * 8 + 2 * tig;
            As[r * 132 + col]           = tf32f(fssp(C[i][j][0] + sbv[col]));
            As[r * 132 + col + 1]       = tf32f(fssp(C[i][j][1] + sbv[col + 1]));
            As[(r + 8) * 132 + col]     = tf32f(fssp(C[i][j][2] + sbv[col]));
            As[(r + 8) * 132 + col + 1] = tf32f(fssp(C[i][j][3] + sbv[col + 1]));
        }
    }
    for (int t = tid; t < 128 * 136; t += 256) {
        int r = t / 136, c = t % 136;
        Bs[t] = (c < 128) ? tf32f(W_o2[r * 128 + c]) : 0.f;
    }
    if (tid < 128) sbv[tid] = b_o2[tid];
    __syncthreads();
    float C2[2][8][4] = {};
    gemm128<16, 132, 136>(As, Bs, C2, tid);
#pragma unroll
    for (int i = 0; i < 2; ++i)
#pragma unroll
        for (int h = 0; h < 2; ++h) {
            int row = r0 + wm + i * 16 + gid + h * 8;
            if (row < N_ATOMS)
#pragma unroll
                for (int j = 0; j < 8; ++j) {
                    int col = wn + j * 8 + 2 * tig;
                    float2 v = make_float2(C2[i][j][h * 2] + sbv[col],
                                           C2[i][j][h * 2 + 1] + sbv[col + 1]);
                    *reinterpret_cast<float2*>(&out[(size_t)row * 128 + col]) = v;
                }
        }
}

extern "C" void kernel_launch(void* const* d_in, const int* in_sizes, int n_in,
                              void* d_out, int out_size) {
    const float* emb  = (const float*)d_in[0];
    const int*   pidx = (const int*)d_in[1];
    const float* fij  = (const float*)d_in[2];
    const float* cut  = (const float*)d_in[3];
    const float* W_in = (const float*)d_in[4];
    const float* W_f1 = (const float*)d_in[5];
    const float* b_f1 = (const float*)d_in[6];
    const float* W_f2 = (const float*)d_in[7];
    const float* b_f2 = (const float*)d_in[8];
    const float* W_o1 = (const float*)d_in[9];
    const float* b_o1 = (const float*)d_in[10];
    const float* W_o2 = (const float*)d_in[11];
    const float* b_o2 = (const float*)d_in[12];
    float* out = (float*)d_out;

    const int smemPair = SMEM_PAIR_F * 4;  // 112640 B
    const int smemGemm = (128 * 132 + 128 * 136 + 128) * 4;

    cudaFuncSetAttribute(k_pair, cudaFuncAttributeMaxDynamicSharedMemorySize, smemPair);
    cudaFuncSetAttribute(k_proj, cudaFuncAttributeMaxDynamicSharedMemorySize, smemGemm);
    cudaFuncSetAttribute(k_out,  cudaFuncAttributeMaxDynamicSharedMemorySize, smemGemm);

    const int NT = N_PAIRS / 128;  // 12500
    k_czero<<<(N_ATOMS + 255) / 256, 256>>>();
    k_bucket<<<(N_PAIRS + 255) / 256, 256>>>(pidx);
    k_proj<<<(N_ATOMS + 127) / 128, 256, smemGemm>>>(emb, W_in);
    k_pair<<<148, 512, smemPair>>>(fij, cut, W_f1, b_f1, W_f2, b_f2, 0, NT / 2);
    k_pair<<<148, 512, smemPair>>>(fij, cut, W_f1, b_f1, W_f2, b_f2, NT / 2, NT - NT / 2);
    k_gather<<<(N_ATOMS * 32 + 255) / 256, 256>>>();
    k_out<<<(N_ATOMS + 127) / 128, 256, smemGemm>>>(W_o1, b_o1, W_o2, b_o2, out);
}

// round 14
// speedup vs baseline: 2.5036x; 1.1703x over previous
#include <cuda_runtime.h>
#include <cuda_fp16.h>
#include <cstdint>

#define N_ATOMS 50000
#define N_PAIRS 1600000
#define LN2F 0.6931471805599453f
#define CAP 96

__device__ float g_x[(size_t)N_ATOMS * 128];
__device__ float g_acc[(size_t)N_ATOMS * 128];
__device__ __half g_wh[(size_t)N_PAIRS * 128];   // cutoff-weighted filters (fp16 storage)
__device__ int   g_cnt[N_ATOMS];
__device__ int2  g_bucket[(size_t)N_ATOMS * CAP];

// ---------------------------------------------------------------------------
// helpers
// ---------------------------------------------------------------------------
__device__ __forceinline__ float fssp(float x) {
    if (x > 60.f) return x - LN2F;
    float t, l;
    asm("ex2.approx.f32 %0, %1;" : "=f"(t) : "f"(x * 1.4426950408889634f));
    asm("lg2.approx.f32 %0, %1;" : "=f"(l) : "f"(t + 1.0f));
    return 0.69314718055994531f * (l - 1.0f);
}
__device__ __forceinline__ void barh(int id) {
    asm volatile("bar.sync %0, 256;" :: "r"(id) : "memory");
}
__device__ __forceinline__ uint32_t packh2(float a, float b) {
    __half2 h = __floats2half2_rn(a, b);
    return *reinterpret_cast<uint32_t*>(&h);
}
__device__ __forceinline__ float2 unpackh2(uint32_t u) {
    __half2 h = *reinterpret_cast<__half2*>(&u);
    return __half22float2(h);
}
__device__ __forceinline__ void mma16(float c[4], const uint32_t a[4], const uint32_t b[2]) {
    asm volatile(
        "mma.sync.aligned.m16n8k16.row.col.f32.f16.f16.f32 "
        "{%0,%1,%2,%3}, {%4,%5,%6,%7}, {%8,%9}, {%0,%1,%2,%3};\n"
        : "+f"(c[0]), "+f"(c[1]), "+f"(c[2]), "+f"(c[3])
        : "r"(a[0]), "r"(a[1]), "r"(a[2]), "r"(a[3]), "r"(b[0]), "r"(b[1]));
}

// ---------------------------------------------------------------------------
// fp16 fragment-major word indexing (m16n8k16) — validated rounds 12/13
// ---------------------------------------------------------------------------
__device__ __forceinline__ int aword(int row, int c, int kst) {
    int f4 = (((row >> 5) * kst + (c >> 4)) * 2 + ((row >> 4) & 1)) * 32
           + (row & 7) * 4 + (((c & 15) & 7) >> 1);
    return f4 * 4 + ((c & 15) >> 3) * 2 + ((row >> 3) & 1);
}
__device__ __forceinline__ int bword(int kk, int n, int kst) {
    int f4 = (n >> 6) * (kst * 128) + (kk >> 4) * 128 + (((n >> 3) & 7) >> 1) * 32
           + (n & 7) * 4 + (((kk & 15) & 7) >> 1);
    return f4 * 4 + ((n >> 3) & 1) * 2 + ((kk & 15) >> 3);
}

// 128x128xK fp16 tile GEMM from fragment-major tiles. 8 warps 4(m)x2(n).
template <int KST>
__device__ __forceinline__ void gemmH(const float* __restrict__ Af,
                                      const float* __restrict__ Bf,
                                      float C[2][8][4], int htid) {
    const int lane = htid & 31, warp = htid >> 5;
    const float4* A4 = (const float4*)Af + (warp >> 1) * (KST * 64) + lane;
    const float4* B4 = (const float4*)Bf + (warp & 1) * (KST * 128) + lane;
#pragma unroll
    for (int k = 0; k < KST; ++k) {
        float4 fa0 = A4[k * 64];
        float4 fa1 = A4[k * 64 + 32];
        uint32_t a[2][4] = {
            {__float_as_uint(fa0.x), __float_as_uint(fa0.y), __float_as_uint(fa0.z), __float_as_uint(fa0.w)},
            {__float_as_uint(fa1.x), __float_as_uint(fa1.y), __float_as_uint(fa1.z), __float_as_uint(fa1.w)}};
        uint32_t b[8][2];
#pragma unroll
        for (int g = 0; g < 4; ++g) {
            float4 fb = B4[k * 128 + g * 32];
            b[2 * g][0] = __float_as_uint(fb.x);
            b[2 * g][1] = __float_as_uint(fb.y);
            b[2 * g + 1][0] = __float_as_uint(fb.z);
            b[2 * g + 1][1] = __float_as_uint(fb.w);
        }
#pragma unroll
        for (int i = 0; i < 2; ++i)
#pragma unroll
            for (int j = 0; j < 8; ++j) mma16(C[i][j], a[i], b[j]);
    }
}

// smem float offsets for k_pair (fp16 tiles, fp16 w-stage)
#define OFF_BF2  0
#define OFF_BF1  8192
#define OFF_BB1  10240
#define OFF_BB2  10368
#define OFF_UNI0 10496
#define UNI_W    8704
#define HALF_STRIDE (UNI_W + 128)
#define SMEM_PAIR_F (OFF_UNI0 + 2 * HALF_STRIDE)  // 28160 f = 112640 B

// smem for k_proj / k_out (fp16 path)
#define SMEM_ATOM_F (8192 + 8192 + 256)   // Af + Bf + 2 biases = 66560 B

// ---------------------------------------------------------------------------
// bucketing
// ---------------------------------------------------------------------------
__global__ void k_czero() {
    int i = blockIdx.x * blockDim.x + threadIdx.x;
    if (i < N_ATOMS) g_cnt[i] = 0;
}
__global__ void k_bucket(const int* __restrict__ pidx) {
    int p = blockIdx.x * blockDim.x + threadIdx.x;
    if (p < N_PAIRS) {
        int i = __ldg(&pidx[p]);
        int j = __ldg(&pidx[N_PAIRS + p]);
        int slot = atomicAdd(&g_cnt[i], 1);
        if (slot < CAP) g_bucket[(size_t)i * CAP + slot] = make_int2(p, j);
    }
}

// ---------------------------------------------------------------------------
// x = atomic_embedding @ W_in -> g_x  (fp16 mma, 2 CTA/SM)
// ---------------------------------------------------------------------------
__global__ __launch_bounds__(256, 2) void k_proj(const float* __restrict__ emb,
                                                 const float* __restrict__ W_in) {
    extern __shared__ float smem[];
    float* Af = smem;
    float* Bf = smem + 8192;
    const int tid = threadIdx.x;
    const int r0 = blockIdx.x * 128;

    for (int t = tid; t < 128 * 64; t += 256) {
        int row = t >> 6, cp = t & 63;
        float2 v = make_float2(0.f, 0.f);
        if (r0 + row < N_ATOMS)
            v = *reinterpret_cast<const float2*>(&emb[(size_t)(r0 + row) * 128 + 2 * cp]);
        ((uint32_t*)Af)[aword(row, 2 * cp, 8)] = packh2(v.x, v.y);
    }
    for (int t = tid; t < 64 * 128; t += 256) {
        int kk = (t >> 7) * 2, n = t & 127;
        ((uint32_t*)Bf)[bword(kk, n, 8)] = packh2(W_in[kk * 128 + n], W_in[(kk + 1) * 128 + n]);
    }
    __syncthreads();

    float C[2][8][4] = {};
    gemmH<8>(Af, Bf, C, tid);

    const int lane = tid & 31, warp = tid >> 5;
    const int wm = (warp >> 1) * 32, wn = (warp & 1) * 64;
    const int gid = lane >> 2, tig = lane & 3;
#pragma unroll
    for (int i = 0; i < 2; ++i)
#pragma unroll
        for (int h = 0; h < 2; ++h) {
            int row = r0 + wm + i * 16 + gid + h * 8;
            if (row < N_ATOMS)
#pragma unroll
                for (int j = 0; j < 8; ++j) {
                    int col = wn + j * 8 + 2 * tig;
                    float2 v = make_float2(C[i][j][h * 2], C[i][j][h * 2 + 1]);
                    *reinterpret_cast<float2*>(&g_x[(size_t)row * 128 + col]) = v;
                }
        }
}

// ---------------------------------------------------------------------------
// Phase A: persistent filter-network GEMMs (fp16 mma); staged fp16 w write.
// ---------------------------------------------------------------------------
__global__ __launch_bounds__(512, 1)
void k_pair(const float* __restrict__ f_ij, const float* __restrict__ cut,
            const float* __restrict__ W_f1, const float* __restrict__ b_f1,
            const float* __restrict__ W_f2, const float* __restrict__ b_f2,
            int tile_base, int tile_count) {
    extern __shared__ float smem[];
    const int tid = threadIdx.x;
    const int half = tid >> 8;
    const int htid = tid & 255;

    float* Bf2 = smem + OFF_BF2;
    float* Bf1 = smem + OFF_BF1;
    float* uni = smem + OFF_UNI0 + half * HALF_STRIDE;
    float* scut = uni + UNI_W;
    uint32_t* uw = (uint32_t*)uni;

    for (int t = tid; t < 64 * 128; t += 512) {
        int kk = (t >> 7) * 2, n = t & 127;
        ((uint32_t*)Bf2)[bword(kk, n, 8)] =
            packh2(W_f2[kk * 128 + n], W_f2[(kk + 1) * 128 + n]);
    }
    for (int t = tid; t < 16 * 128; t += 512) {
        int kk = (t >> 7) * 2, n = t & 127;
        float v0 = (kk < 20) ? W_f1[kk * 128 + n] : 0.f;
        float v1 = (kk + 1 < 20) ? W_f1[(kk + 1) * 128 + n] : 0.f;
        ((uint32_t*)Bf1)[bword(kk, n, 2)] = packh2(v0, v1);
    }
    if (tid < 128) smem[OFF_BB1 + tid] = b_f1[tid];
    else if (tid < 256) smem[OFF_BB2 + tid - 128] = b_f2[tid - 128];
    __syncthreads();

    const float* b1s = smem + OFF_BB1;
    const float* b2s = smem + OFF_BB2;
    const int bar = 1 + half;
    const int lane = htid & 31, warp = htid >> 5;
    const int wm = (warp >> 1) * 32, wn = (warp & 1) * 64;
    const int gid = lane >> 2, tig = lane & 3;

    const int end = tile_base + tile_count;
    const int step = (int)gridDim.x * 2;
    int tile = tile_base + (int)blockIdx.x * 2 + half;
    if (tile >= end) return;

    const int prow = htid >> 1;
    const int podd = htid & 1;
    const int pcol = podd * 10;
    float pf[10];
    float pcut = 0.f;
    {
        const float* src = f_ij + (size_t)(tile * 128 + prow) * 20 + pcol;
#pragma unroll
        for (int q = 0; q < 10; ++q) pf[q] = __ldg(src + q);
        if (htid < 128) pcut = __ldg(&cut[tile * 128 + htid]);
    }

    float4* A2v = (float4*)uni + (((warp >> 1) * 8 + (wn >> 4)) * 2) * 32 + lane;

    for (; tile < end; tile += step) {
        const int p0 = tile * 128;

        // S1: prefetched f_ij -> fp16 fragment words (incl. zero pad)
        if (!podd) {
#pragma unroll
            for (int q = 0; q < 5; ++q)
                uw[aword(prow, q * 2, 2)] = packh2(pf[2 * q], pf[2 * q + 1]);
        } else {
#pragma unroll
            for (int q = 0; q < 5; ++q)
                uw[aword(prow, 10 + q * 2, 2)] = packh2(pf[2 * q], pf[2 * q + 1]);
#pragma unroll
            for (int q = 0; q < 6; ++q)
                uw[aword(prow, 20 + q * 2, 2)] = 0u;
        }
        if (htid < 128) scut[htid] = pcut;
        barh(bar);

        int nt = tile + step;
        if (nt < end) {
            const float* src = f_ij + (size_t)(nt * 128 + prow) * 20 + pcol;
#pragma unroll
            for (int q = 0; q < 10; ++q) pf[q] = __ldg(src + q);
            if (htid < 128) pcut = __ldg(&cut[nt * 128 + htid]);
        }

        // GEMM1 (K=32 incl pad -> 2 ksteps, fp16)
        float C[2][8][4] = {};
        gemmH<2>(uni, Bf1, C, htid);
        barh(bar);

        // S3: hidden = fp16(fssp(C+b1)) -> A2 fragments
#pragma unroll
        for (int i = 0; i < 2; ++i) {
#pragma unroll
            for (int q = 0; q < 4; ++q) {
                int c0 = wn + q * 16 + 2 * tig;
                int c1 = c0 + 8;
                float4 o;
                o.x = __uint_as_float(packh2(fssp(C[i][2 * q][0] + b1s[c0]),
                                             fssp(C[i][2 * q][1] + b1s[c0 + 1])));
                o.y = __uint_as_float(packh2(fssp(C[i][2 * q][2] + b1s[c0]),
                                             fssp(C[i][2 * q][3] + b1s[c0 + 1])));
                o.z = __uint_as_float(packh2(fssp(C[i][2 * q + 1][0] + b1s[c1]),
                                             fssp(C[i][2 * q + 1][1] + b1s[c1 + 1])));
                o.w = __uint_as_float(packh2(fssp(C[i][2 * q + 1][2] + b1s[c1]),
                                             fssp(C[i][2 * q + 1][3] + b1s[c1 + 1])));
                A2v[(q * 2 + i) * 32] = o;
            }
        }
        barh(bar);

        // GEMM2 (K=128 -> 8 ksteps, fp16)
        float C2[2][8][4] = {};
        gemmH<8>(uni, Bf2, C2, htid);
        barh(bar);

        // stage w = fp16((C2+b2)*cut) as h2 words, rows stride 68
#pragma unroll
        for (int i = 0; i < 2; ++i)
#pragma unroll
            for (int h = 0; h < 2; ++h) {
                int r = wm + i * 16 + gid + h * 8;
                float ct = scut[r];
#pragma unroll
                for (int j = 0; j < 8; ++j) {
                    int c2 = (wn >> 1) + j * 4 + tig;
                    uw[r * 68 + c2] = packh2((C2[i][j][h * 2] + b2s[2 * c2]) * ct,
                                             (C2[i][j][h * 2 + 1] + b2s[2 * c2 + 1]) * ct);
                }
            }
        barh(bar);

        // coalesced fp16 write-out: warp = full 256B rows
#pragma unroll
        for (int rr = 0; rr < 16; ++rr) {
            int row = warp * 16 + rr;
            uint2 v = make_uint2(uw[row * 68 + lane * 2], uw[row * 68 + lane * 2 + 1]);
            ((uint2*)(g_wh + (size_t)(p0 + row) * 128))[lane] = v;
        }
        barh(bar);
    }
}

// ---------------------------------------------------------------------------
// Phase B: one warp per atom sums w[p] * x[j], unrolled x2 for MLP
// ---------------------------------------------------------------------------
__global__ __launch_bounds__(256, 2) void k_gather() {
    int atom = (blockIdx.x * 256 + threadIdx.x) >> 5;
    int lane = threadIdx.x & 31;
    if (atom >= N_ATOMS) return;
    int cnt = __ldg(&g_cnt[atom]);
    if (cnt > CAP) cnt = CAP;
    const int2* bucket = g_bucket + (size_t)atom * CAP;
    float4 acc = make_float4(0.f, 0.f, 0.f, 0.f);

    int t = 0;
    for (; t + 2 <= cnt; t += 2) {
        int2 e0 = __ldg(&bucket[t]);
        int2 e1 = __ldg(&bucket[t + 1]);
        uint2 w0 = __ldg((const uint2*)(g_wh + (size_t)e0.x * 128) + lane);
        float4 x0 = __ldg((const float4*)(g_x + (size_t)e0.y * 128) + lane);
        uint2 w1 = __ldg((const uint2*)(g_wh + (size_t)e1.x * 128) + lane);
        float4 x1 = __ldg((const float4*)(g_x + (size_t)e1.y * 128) + lane);
        float2 a0 = unpackh2(w0.x), b0 = unpackh2(w0.y);
        float2 a1 = unpackh2(w1.x), b1 = unpackh2(w1.y);
        acc.x += a0.x * x0.x; acc.y += a0.y * x0.y;
        acc.z += b0.x * x0.z; acc.w += b0.y * x0.w;
        acc.x += a1.x * x1.x; acc.y += a1.y * x1.y;
        acc.z += b1.x * x1.z; acc.w += b1.y * x1.w;
    }
    if (t < cnt) {
        int2 e = __ldg(&bucket[t]);
        uint2 w = __ldg((const uint2*)(g_wh + (size_t)e.x * 128) + lane);
        float4 x = __ldg((const float4*)(g_x + (size_t)e.y * 128) + lane);
        float2 a = unpackh2(w.x), b = unpackh2(w.y);
        acc.x += a.x * x.x; acc.y += a.y * x.y;
        acc.z += b.x * x.z; acc.w += b.y * x.w;
    }
    *((float4*)(g_acc + (size_t)atom * 128) + lane) = acc;
}

// ---------------------------------------------------------------------------
// Output MLP (fp16 mma, 2 CTA/SM)
// ---------------------------------------------------------------------------
__global__ __launch_bounds__(256, 2) void k_out(const float* __restrict__ W_o1,
                                                const float* __restrict__ b_o1,
                                                const float* __restrict__ W_o2,
                                                const float* __restrict__ b_o2,
                                                float* __restrict__ out) {
    extern __shared__ float smem[];
    float* Af = smem;
    float* Bf = smem + 8192;
    float* sb1 = smem + 16384;
    float* sb2 = smem + 16512;
    const int tid = threadIdx.x;
    const int r0 = blockIdx.x * 128;

    for (int t = tid; t < 128 * 64; t += 256) {
        int row = t >> 6, cp = t & 63;
        float2 v = make_float2(0.f, 0.f);
        if (r0 + row < N_ATOMS)
            v = *reinterpret_cast<const float2*>(&g_acc[(size_t)(r0 + row) * 128 + 2 * cp]);
        ((uint32_t*)Af)[aword(row, 2 * cp, 8)] = packh2(v.x, v.y);
    }
    for (int t = tid; t < 64 * 128; t += 256) {
        int kk = (t >> 7) * 2, n = t & 127;
        ((uint32_t*)Bf)[bword(kk, n, 8)] = packh2(W_o1[kk * 128 + n], W_o1[(kk + 1) * 128 + n]);
    }
    if (tid < 128) sb1[tid] = b_o1[tid];
    else sb2[tid - 128] = b_o2[tid - 128];
    __syncthreads();

    float C[2][8][4] = {};
    gemmH<8>(Af, Bf, C, tid);
    __syncthreads();  // all reads of Af/Bf done

    const int lane = tid & 31, warp = tid >> 5;
    const int wm = (warp >> 1) * 32, wn = (warp & 1) * 64;
    const int gid = lane >> 2, tig = lane & 3;

    // repack: hidden = fp16(fssp(C + b_o1)) -> Af fragments (A2v pattern)
    float4* A2v = (float4*)Af + (((warp >> 1) * 8 + (wn >> 4)) * 2) * 32 + lane;
#pragma unroll
    for (int i = 0; i < 2; ++i) {
#pragma unroll
        for (int q = 0; q < 4; ++q) {
            int c0 = wn + q * 16 + 2 * tig;
            int c1 = c0 + 8;
            float4 o;
            o.x = __uint_as_float(packh2(fssp(C[i][2 * q][0] + sb1[c0]),
                                         fssp(C[i][2 * q][1] + sb1[c0 + 1])));
            o.y = __uint_as_float(packh2(fssp(C[i][2 * q][2] + sb1[c0]),
                                         fssp(C[i][2 * q][3] + sb1[c0 + 1])));
            o.z = __uint_as_float(packh2(fssp(C[i][2 * q + 1][0] + sb1[c1]),
                                         fssp(C[i][2 * q + 1][1] + sb1[c1 + 1])));
            o.w = __uint_as_float(packh2(fssp(C[i][2 * q + 1][2] + sb1[c1]),
                                         fssp(C[i][2 * q + 1][3] + sb1[c1 + 1])));
            A2v[(q * 2 + i) * 32] = o;
        }
    }
    // restage B with W_o2
    for (int t = tid; t < 64 * 128; t += 256) {
        int kk = (t >> 7) * 2, n = t & 127;
        ((uint32_t*)Bf)[bword(kk, n, 8)] = packh2(W_o2[kk * 128 + n], W_o2[(kk + 1) * 128 + n]);
    }
    __syncthreads();

    float C2[2][8][4] = {};
    gemmH<8>(Af, Bf, C2, tid);

#pragma unroll
    for (int i = 0; i < 2; ++i)
#pragma unroll
        for (int h = 0; h < 2; ++h) {
            int row = r0 + wm + i * 16 + gid + h * 8;
            if (row < N_ATOMS)
#pragma unroll
                for (int j = 0; j < 8; ++j) {
                    int col = wn + j * 8 + 2 * tig;
                    float2 v = make_float2(C2[i][j][h * 2] + sb2[col],
                                           C2[i][j][h * 2 + 1] + sb2[col + 1]);
                    *reinterpret_cast<float2*>(&out[(size_t)row * 128 + col]) = v;
                }
        }
}

extern "C" void kernel_launch(void* const* d_in, const int* in_sizes, int n_in,
                              void* d_out, int out_size) {
    const float* emb  = (const float*)d_in[0];
    const int*   pidx = (const int*)d_in[1];
    const float* fij  = (const float*)d_in[2];
    const float* cut  = (const float*)d_in[3];
    const float* W_in = (const float*)d_in[4];
    const float* W_f1 = (const float*)d_in[5];
    const float* b_f1 = (const float*)d_in[6];
    const float* W_f2 = (const float*)d_in[7];
    const float* b_f2 = (const float*)d_in[8];
    const float* W_o1 = (const float*)d_in[9];
    const float* b_o1 = (const float*)d_in[10];
    const float* W_o2 = (const float*)d_in[11];
    const float* b_o2 = (const float*)d_in[12];
    float* out = (float*)d_out;

    const int smemPair = SMEM_PAIR_F * 4;   // 112640 B
    const int smemAtom = SMEM_ATOM_F * 4;   // 66560 B

    cudaFuncSetAttribute(k_pair, cudaFuncAttributeMaxDynamicSharedMemorySize, smemPair);
    cudaFuncSetAttribute(k_proj, cudaFuncAttributeMaxDynamicSharedMemorySize, smemAtom);
    cudaFuncSetAttribute(k_out,  cudaFuncAttributeMaxDynamicSharedMemorySize, smemAtom);

    const int NT = N_PAIRS / 128;  // 12500
    k_czero<<<(N_ATOMS + 255) / 256, 256>>>();
    k_bucket<<<(N_PAIRS + 255) / 256, 256>>>(pidx);
    k_proj<<<(N_ATOMS + 127) / 128, 256, smemAtom>>>(emb, W_in);
    k_pair<<<148, 512, smemPair>>>(fij, cut, W_f1, b_f1, W_f2, b_f2, 0, NT / 2);
    k_pair<<<148, 512, smemPair>>>(fij, cut, W_f1, b_f1, W_f2, b_f2, NT / 2, NT - NT / 2);
    k_gather<<<(N_ATOMS * 32 + 255) / 256, 256>>>();
    k_out<<<(N_ATOMS + 127) / 128, 256, smemAtom>>>(W_o1, b_o1, W_o2, b_o2, out);
}